// round 4
// baseline (speedup 1.0000x reference)
#include <cuda_runtime.h>

#define NB 64       // batch
#define NT 512      // seq len
#define NE 256      // embed dim
#define NH 256      // hidden
#define NGATE 1024  // 4*NH
#define NK 9        // tags
#define NCTA 128    // persistent LSTM grid (64 per direction)

typedef unsigned long long u64;

// ---------------- packed fp32x2 helpers (sm_103a FFMA2) ---------------------
__device__ __forceinline__ void fma2(u64& d, u64 a, u64 b) {
    asm("fma.rn.f32x2 %0, %1, %2, %0;" : "+l"(d) : "l"(a), "l"(b));
}
__device__ __forceinline__ u64 pk2(float x, float y) {
    u64 r; asm("mov.b64 %0, {%1,%2};" : "=l"(r) : "f"(x), "f"(y)); return r;
}
__device__ __forceinline__ unsigned smem_u32(const void* p) {
    return (unsigned)__cvta_generic_to_shared(p);
}
__device__ __forceinline__ void cp16(unsigned dst, const void* src) {
    asm volatile("cp.async.cg.shared.global [%0], [%1], 16;" :: "r"(dst), "l"(src));
}
__device__ __forceinline__ void cp_commit() {
    asm volatile("cp.async.commit_group;");
}
#define CP_WAIT(n) asm volatile("cp.async.wait_group %0;" :: "n"(n))
__device__ __forceinline__ unsigned ldvol(const unsigned* p) {
    unsigned v;
    asm volatile("ld.volatile.global.u32 %0, [%1];" : "=r"(v) : "l"(p));
    return v;
}

// ---------------- scratch (__device__ globals; no allocation APIs) ----------
__device__ float d_gx[(size_t)2 * NT * NGATE * NB];     // [dir][t][gate][b]
__device__ float d_hs[(size_t)2 * NT * NH * NB];        // [dir][t][j][b]
__device__ float d_feats[(size_t)NB * NT * 2 * NH];     // [b][t][2H]
__device__ float d_em[(size_t)NB * NT * NK];            // [b][t][k]
__device__ int d_preds[NB * NT];
__device__ float d_loss_partial[NB];
__device__ float d_loss;
// per-(dir,t,chunk-group,warp) arrival counters; 16 producers each
__device__ unsigned int d_flag[2 * NT * 4 * 4];

__global__ void k_init() {
    int i = blockIdx.x * 256 + threadIdx.x;
    if (i < 2 * NT * 4 * 4) d_flag[i] = 0u;
}

// ---------------- input projection: gx[dir][t][g][b] = W_ih[g]·emb + b ------
__global__ __launch_bounds__(256) void k_gx(
    const int* __restrict__ widx, const int* __restrict__ lens,
    const float* __restrict__ wvec,
    const float* __restrict__ Wih_f, const float* __restrict__ b_f,
    const float* __restrict__ Wih_b, const float* __restrict__ b_b)
{
    __shared__ float4 sWd[64 * 32];       // [row-pair][col] dup: (w0,w0,w1,w1)
    __shared__ float sXT[32 * 66];        // [e][b]
    __shared__ int rowidx[64];
    const int t = blockIdx.y;
    const int dir = blockIdx.z;
    const int g0 = blockIdx.x * 128;
    const float* Wih = dir ? Wih_b : Wih_f;
    const float* bias = dir ? b_b : b_f;
    const int tid = threadIdx.x;
    if (tid < 64) {
        int len = lens[tid];
        int tt = t;
        if (dir) tt = (t < len) ? (len - 1 - t) : t;  // reversed sequence
        rowidx[tid] = widx[tid * NT + tt];            // fused embedding gather
    }
    const int bg = tid & 15;   // batch group (4 batches)
    const int gg = tid >> 4;   // gate-row group (8 rows)
    u64 acc[8][2];
#pragma unroll
    for (int u = 0; u < 8; u++) {
        float bv = bias[g0 + gg * 8 + u];
        acc[u][0] = pk2(bv, bv);
        acc[u][1] = acc[u][0];
    }
    for (int e0 = 0; e0 < NE; e0 += 32) {
        __syncthreads();
#pragma unroll
        for (int i = 0; i < 16; i++) {            // W slice, duplicated pairs
            int idx = tid + i * 256;
            int r = idx >> 5, c = idx & 31;
            float w = Wih[(size_t)(g0 + r) * NE + e0 + c];
            float* dst = (float*)&sWd[(r >> 1) * 32 + c];
            dst[(r & 1) * 2 + 0] = w;
            dst[(r & 1) * 2 + 1] = w;
        }
#pragma unroll
        for (int i = 0; i < 8; i++) {             // X transposed [e][b]
            int idx = tid + i * 256;
            int r = idx >> 5, c = idx & 31;
            sXT[c * 66 + r] = wvec[(size_t)rowidx[r] * NE + e0 + c];
        }
        __syncthreads();
#pragma unroll
        for (int kk = 0; kk < 32; kk++) {
            u64 x01 = *(const u64*)&sXT[kk * 66 + bg * 4];
            u64 x23 = *(const u64*)&sXT[kk * 66 + bg * 4 + 2];
#pragma unroll
            for (int up = 0; up < 4; up++) {
                ulonglong2 wq = *(const ulonglong2*)&sWd[(gg * 4 + up) * 32 + kk];
                fma2(acc[up * 2 + 0][0], wq.x, x01);
                fma2(acc[up * 2 + 0][1], wq.x, x23);
                fma2(acc[up * 2 + 1][0], wq.y, x01);
                fma2(acc[up * 2 + 1][1], wq.y, x23);
            }
        }
    }
    float* gout = d_gx + ((size_t)(dir * NT + t) * NGATE + g0) * NB;
#pragma unroll
    for (int u = 0; u < 8; u++) {
        *(u64*)(gout + (gg * 8 + u) * NB + bg * 4) = acc[u][0];
        *(u64*)(gout + (gg * 8 + u) * NB + bg * 4 + 2) = acc[u][1];
    }
}

// ---------------- persistent bidirectional LSTM recurrence ------------------
// 128 CTAs (64/dir), 128 threads. NO global barrier: per-(t,chunk,warp) flags.
// Warps are fully decoupled pipelines: each warp owns 16 batches, loads only
// its own h slice via cp.async, exchanges gates via __syncwarp only.
// smem floats: WsP 8192 | hs 16384 | sgx 2048 | g_sm 1024  -> 27648 (108 KB)
#define LSTM_SMEM_FLOATS (8192 + 16384 + 2048 + 1024)
__global__ __launch_bounds__(128, 1) void k_lstm(
    const float* __restrict__ Whh_f, const float* __restrict__ Whh_b)
{
    extern __shared__ float smem[];
    float* WsPf = smem;                      // float4[8*256] dup row pairs
    float* hs = smem + 8192;                 // [warp][k=256][16 batches]
    float* sgx = smem + 8192 + 16384;        // [warp][2][16 rows][16 batches]
    float* g_sm = smem + 8192 + 16384 + 2048;// [warp][16 rows][16 batches]
    const int tid = threadIdx.x;
    const int lane = tid & 31, w = tid >> 5;
    const int dir = blockIdx.x >> 6;
    const int p = blockIdx.x & 63;           // producer index within dir
    const int j0 = p * 4;                    // 4 hidden units per CTA
    const int pg = p >> 4;                   // chunk-group this CTA feeds
    const float* Whh = dir ? Whh_b : Whh_f;
#pragma unroll
    for (int i = 0; i < 16; i++) {           // W_hh slice, duplicated pairs
        int idx = tid + i * 128;
        int rp = idx >> 8, k = idx & 255;
        int rl0 = rp * 2;
        int q = rl0 >> 2, jj = rl0 & 3;
        float w0 = Whh[(size_t)(q * NH + j0 + jj) * NH + k];
        float w1 = Whh[(size_t)(q * NH + j0 + jj + 1) * NH + k];
        ((float4*)WsPf)[rp * 256 + k] = make_float4(w0, w0, w1, w1);
    }
    __syncthreads();
    const int r2 = lane >> 2;                // row pair (rows 2r2, 2r2+1)
    const int bq = lane & 3;                 // batch quad within warp
    const int row0 = r2 * 2;
    const int jj = lane >> 4;                // finalize: units jj, jj+2
    const int bl = lane & 15;
    float cA = 0.f, cB = 0.f;
    const unsigned hs_b = smem_u32(hs + w * 4096);
    const unsigned sgx_b = smem_u32(sgx + w * 512);
    const float* hw = hs + w * 4096;
    const ulonglong2* wp = (const ulonglong2*)WsPf + r2 * 256;
    float* gw = g_sm + w * 256;
    // prefetch gx(0)
    {
        const float* gsrc = d_gx + (size_t)(dir * NT + 0) * NGATE * NB;
#pragma unroll
        for (int i = 0; i < 2; i++) {
            int idx = i * 32 + lane;
            int row = idx >> 2, pc = idx & 3;
            int grl = (row >> 2) * NH + j0 + (row & 3);
            cp16(sgx_b + (0 * 256 + row * 16 + pc * 4) * 4,
                 gsrc + (size_t)grl * NB + w * 16 + pc * 4);
        }
        cp_commit();
    }
    for (int t = 0; t < NT; t++) {
        if (t > 0) {
            const float* hsrc = d_hs + (size_t)(dir * NT + t - 1) * NH * NB;
            const unsigned* fbase = &d_flag[((dir * NT + t - 1) * 4) * 4 + w];
#pragma unroll
            for (int c = 0; c < 4; c++) {
                if (lane == 0) {
                    while (ldvol(fbase + c * 4) < 16u) __nanosleep(8);
                }
                __syncwarp();
                __threadfence();   // acquire side
#pragma unroll
                for (int i = 0; i < 8; i++) {
                    int idx = i * 32 + lane;
                    int kl = idx >> 2, pc = idx & 3;
                    int k = c * 64 + kl;
                    cp16(hs_b + (k * 16 + pc * 4) * 4,
                         hsrc + (size_t)k * NB + w * 16 + pc * 4);
                }
                cp_commit();
            }
        }
        {   // prefetch gx(t+1)
            int tp = (t + 1 < NT) ? t + 1 : t;
            const float* gsrc = d_gx + (size_t)(dir * NT + tp) * NGATE * NB;
#pragma unroll
            for (int i = 0; i < 2; i++) {
                int idx = i * 32 + lane;
                int row = idx >> 2, pc = idx & 3;
                int grl = (row >> 2) * NH + j0 + (row & 3);
                cp16(sgx_b + ((tp & 1) * 256 + row * 16 + pc * 4) * 4,
                     gsrc + (size_t)grl * NB + w * 16 + pc * 4);
            }
            cp_commit();
        }
        if (t > 0) { CP_WAIT(5); } else { CP_WAIT(1); }   // gx(t) resident
        const float* gx_s = sgx + w * 512 + (t & 1) * 256;
        u64 a00 = *(const u64*)(gx_s + row0 * 16 + bq * 4);
        u64 a01 = *(const u64*)(gx_s + row0 * 16 + bq * 4 + 2);
        u64 a10 = *(const u64*)(gx_s + (row0 + 1) * 16 + bq * 4);
        u64 a11 = *(const u64*)(gx_s + (row0 + 1) * 16 + bq * 4 + 2);
        if (t > 0) {
#pragma unroll
            for (int c = 0; c < 4; c++) {
                if (c == 0) { CP_WAIT(4); }
                else if (c == 1) { CP_WAIT(3); }
                else if (c == 2) { CP_WAIT(2); }
                else { CP_WAIT(1); }
#pragma unroll 16
                for (int k = c * 64; k < c * 64 + 64; k++) {
                    ulonglong2 wq = wp[k];
                    ulonglong2 hq = *(const ulonglong2*)(hw + k * 16 + bq * 4);
                    fma2(a00, wq.x, hq.x);
                    fma2(a01, wq.x, hq.y);
                    fma2(a10, wq.y, hq.x);
                    fma2(a11, wq.y, hq.y);
                }
            }
        }
        // warp-local gate exchange
        *(u64*)(gw + row0 * 16 + bq * 4) = a00;
        *(u64*)(gw + row0 * 16 + bq * 4 + 2) = a01;
        *(u64*)(gw + (row0 + 1) * 16 + bq * 4) = a10;
        *(u64*)(gw + (row0 + 1) * 16 + bq * 4 + 2) = a11;
        __syncwarp();
        float* hout = d_hs + (size_t)((dir * NT + t) * NH + j0) * NB + w * 16;
        {
            float gi = gw[(0 * 4 + jj) * 16 + bl];
            float gf = gw[(1 * 4 + jj) * 16 + bl];
            float gc = gw[(2 * 4 + jj) * 16 + bl];
            float go = gw[(3 * 4 + jj) * 16 + bl];
            float si = 1.f / (1.f + __expf(-gi));
            float sf = 1.f / (1.f + __expf(-gf));
            float so = 1.f / (1.f + __expf(-go));
            cA = sf * cA + si * tanhf(gc);
            hout[jj * NB + bl] = so * tanhf(cA);
        }
        {
            int j2 = jj + 2;
            float gi = gw[(0 * 4 + j2) * 16 + bl];
            float gf = gw[(1 * 4 + j2) * 16 + bl];
            float gc = gw[(2 * 4 + j2) * 16 + bl];
            float go = gw[(3 * 4 + j2) * 16 + bl];
            float si = 1.f / (1.f + __expf(-gi));
            float sf = 1.f / (1.f + __expf(-gf));
            float so = 1.f / (1.f + __expf(-go));
            cB = sf * cB + si * tanhf(gc);
            hout[j2 * NB + bl] = so * tanhf(cB);
        }
        __syncwarp();
        __threadfence();   // release side
        if (lane == 0)
            atomicAdd(&d_flag[((dir * NT + t) * 4 + pg) * 4 + w], 1u);
        __syncwarp();
    }
}

// ---------------- feats: [b][t][2H] = mask * [h_fwd | h_bwd(unreversed)] ----
__global__ __launch_bounds__(256) void k_feats(const int* __restrict__ lens)
{
    __shared__ float tile[64][65];
    __shared__ int slen[64];
    const int ts = blockIdx.x;          // SOURCE time (keeps writes coalesced)
    const int j0 = blockIdx.y * 64;
    const int dir = blockIdx.z;
    const int tid = threadIdx.x;
    if (tid < 64) slen[tid] = lens[tid];
    const int b = tid & 63, jl = tid >> 6;
    const float* hsrc = d_hs + (size_t)((dir * NT + ts) * NH + j0) * NB;
#pragma unroll
    for (int i = 0; i < 16; i++)
        tile[jl + i * 4][b] = hsrc[(jl + i * 4) * NB + b];
    __syncthreads();
    const int jj = tid & 63, br = tid >> 6;
#pragma unroll
    for (int i = 0; i < 16; i++) {
        int bb = br * 16 + i;
        int len = slen[bb];
        bool valid = ts < len;
        int tout = dir ? (valid ? (len - 1 - ts) : ts) : ts;
        float v = valid ? tile[jj][bb] : 0.f;
        d_feats[(size_t)(bb * NT + tout) * (2 * NH) + dir * NH + j0 + jj] = v;
    }
}

// ---------------- emissions = feats @ W_out^T + b_out -----------------------
__global__ __launch_bounds__(256) void k_emis(const float* __restrict__ Wout,
                                              const float* __restrict__ bout)
{
    __shared__ float sW[NK * 512];
    const int tid = threadIdx.x;
    for (int i = tid; i < NK * 512; i += 256) sW[i] = Wout[i];
    __syncthreads();
    const int lane = tid & 31, warp = tid >> 5;
    const size_t bt = (size_t)blockIdx.x * 8 + warp;
    const float* f = d_feats + bt * 512;
    float x[16];
#pragma unroll
    for (int i = 0; i < 16; i++) x[i] = f[lane + i * 32];
#pragma unroll
    for (int k = 0; k < NK; k++) {
        float acc = 0.f;
#pragma unroll
        for (int i = 0; i < 16; i++) acc += x[i] * sW[k * 512 + lane + i * 32];
#pragma unroll
        for (int off = 16; off; off >>= 1)
            acc += __shfl_xor_sync(0xffffffffu, acc, off);
        if (lane == 0) d_em[bt * NK + k] = acc + bout[k];
    }
}

// ---------------- CRF: numerator + alpha (logZ) + Viterbi + backtrace -------
__global__ void k_crf(const int* __restrict__ lens, const int* __restrict__ labels,
                      const float* __restrict__ stt, const float* __restrict__ ett,
                      const float* __restrict__ trans)
{
    __shared__ unsigned char hist[NT][NK];
    const int b = blockIdx.x;
    const int lane = threadIdx.x;
    const int len = lens[b];
    const float* em = d_em + (size_t)b * NT * NK;
    const int* lab = labels + b * NT;
    const int j = (lane < NK) ? lane : 0;
    float tr[NK];
#pragma unroll
    for (int i = 0; i < NK; i++) tr[i] = trans[i * NK + j];
    float sA = stt[j] + em[j];
    float sV = sA;
    int yprev = lab[0];
    float num = stt[yprev] + em[yprev];
    for (int t = 1; t < NT; t++) {
        float e = em[t * NK + j];
        bool m = t < len;
        float aA[NK], aV[NK];
#pragma unroll
        for (int i = 0; i < NK; i++) {
            aA[i] = __shfl_sync(0xffffffffu, sA, i) + tr[i];
            aV[i] = __shfl_sync(0xffffffffu, sV, i) + tr[i];
        }
        float mA = aA[0];
#pragma unroll
        for (int i = 1; i < NK; i++) mA = fmaxf(mA, aA[i]);
        float ssum = 0.f;
#pragma unroll
        for (int i = 0; i < NK; i++) ssum += __expf(aA[i] - mA);
        float nA = mA + __logf(ssum) + e;
        float mV = aV[0]; int bp = 0;
#pragma unroll
        for (int i = 1; i < NK; i++) { if (aV[i] > mV) { mV = aV[i]; bp = i; } }
        float nV = mV + e;
        if (lane < NK) hist[t][lane] = (unsigned char)bp;
        if (m) { sA = nA; sV = nV; }
        if (lane == 0) {
            int y = lab[t];
            if (m) num += trans[yprev * NK + y] + em[t * NK + y];
            yprev = y;
        }
    }
    float fA = sA + ett[j];
    float fV = sV + ett[j];
    float gA[NK], gV[NK];
#pragma unroll
    for (int i = 0; i < NK; i++) {
        gA[i] = __shfl_sync(0xffffffffu, fA, i);
        gV[i] = __shfl_sync(0xffffffffu, fV, i);
    }
    __syncwarp();
    if (lane == 0) {
        float mA = gA[0];
#pragma unroll
        for (int i = 1; i < NK; i++) mA = fmaxf(mA, gA[i]);
        float ssum = 0.f;
#pragma unroll
        for (int i = 0; i < NK; i++) ssum += __expf(gA[i] - mA);
        float denom = mA + __logf(ssum);
        int bl = 0; float mV = gV[0];
#pragma unroll
        for (int i = 1; i < NK; i++) { if (gV[i] > mV) { mV = gV[i]; bl = i; } }
        num += ett[lab[len - 1]];
        d_loss_partial[b] = num - denom;
        int cur = bl;
        d_preds[b * NT + NT - 1] = (NT - 1 < len) ? cur : 0;
        for (int t = NT - 2; t >= 0; t--) {
            if (t + 1 < len) cur = (int)hist[t + 1][cur];
            d_preds[b * NT + t] = (t < len) ? cur : 0;
        }
    }
}

__global__ void k_loss() {
    float s = 0.f;
    for (int i = 0; i < NB; i++) s += d_loss_partial[i];
    d_loss = -s / (float)NB;
}

// output layout: [loss(1), preds(B*T), feats(B*T*2H)] as float32, prefix-safe.
__global__ void k_writeout(float* __restrict__ out, int n) {
    int i = blockIdx.x * 256 + threadIdx.x;
    if (i >= n) return;
    float v = 0.f;
    if (i == 0) v = d_loss;
    else if (i < 1 + NB * NT) v = (float)d_preds[i - 1];
    else if (i < 1 + NB * NT + NB * NT * 2 * NH) v = d_feats[i - 1 - NB * NT];
    out[i] = v;
}

extern "C" void kernel_launch(void* const* d_in, const int* in_sizes, int n_in,
                              void* d_out, int out_size) {
    const int* widx = (const int*)d_in[0];
    const int* lens = (const int*)d_in[1];
    const int* labels = (const int*)d_in[2];
    const float* wvec = (const float*)d_in[3];
    const float* Wih_f = (const float*)d_in[4];
    const float* Whh_f = (const float*)d_in[5];
    const float* b_f = (const float*)d_in[6];
    const float* Wih_b = (const float*)d_in[7];
    const float* Whh_b = (const float*)d_in[8];
    const float* b_b = (const float*)d_in[9];
    const float* Wout = (const float*)d_in[10];
    const float* bout = (const float*)d_in[11];
    const float* stt = (const float*)d_in[12];
    const float* ett = (const float*)d_in[13];
    const float* trans = (const float*)d_in[14];

    k_init<<<64, 256>>>();

    dim3 gg(NGATE / 128, NT, 2);
    k_gx<<<gg, 256>>>(widx, lens, wvec, Wih_f, b_f, Wih_b, b_b);

    int smem_bytes = LSTM_SMEM_FLOATS * 4;
    cudaFuncSetAttribute(k_lstm, cudaFuncAttributeMaxDynamicSharedMemorySize,
                         smem_bytes);
    k_lstm<<<NCTA, 128, smem_bytes>>>(Whh_f, Whh_b);

    dim3 gf(NT, NH / 64, 2);
    k_feats<<<gf, 256>>>(lens);

    k_emis<<<NB * NT / 8, 256>>>(Wout, bout);
    k_crf<<<NB, 32>>>(lens, labels, stt, ett, trans);
    k_loss<<<1, 1>>>();

    k_writeout<<<(out_size + 255) / 256, 256>>>((float*)d_out, out_size);
}

// round 6
// speedup vs baseline: 1.3539x; 1.3539x over previous
#include <cuda_runtime.h>

#define NB 64       // batch
#define NT 512      // seq len
#define NE 256      // embed dim
#define NH 256      // hidden
#define NGATE 1024  // 4*NH
#define NK 9        // tags
#define NCTA 128    // persistent LSTM grid (64 per direction)

typedef unsigned long long u64;

// ---------------- packed fp32x2 helpers (sm_103a FFMA2) ---------------------
__device__ __forceinline__ void fma2(u64& d, u64 a, u64 b) {
    asm("fma.rn.f32x2 %0, %1, %2, %0;" : "+l"(d) : "l"(a), "l"(b));
}
__device__ __forceinline__ u64 pk2(float x, float y) {
    u64 r; asm("mov.b64 %0, {%1,%2};" : "=l"(r) : "f"(x), "f"(y)); return r;
}
__device__ __forceinline__ unsigned smem_u32(const void* p) {
    return (unsigned)__cvta_generic_to_shared(p);
}
__device__ __forceinline__ void cp16(unsigned dst, const void* src) {
    asm volatile("cp.async.cg.shared.global [%0], [%1], 16;" :: "r"(dst), "l"(src));
}
__device__ __forceinline__ void cp_commit() {
    asm volatile("cp.async.commit_group;");
}
#define CP_WAIT(n) asm volatile("cp.async.wait_group %0;" :: "n"(n))
__device__ __forceinline__ void red_release(unsigned* p) {
    asm volatile("red.release.gpu.global.add.u32 [%0], 1;" :: "l"(p) : "memory");
}
__device__ __forceinline__ unsigned ld_acquire(const unsigned* p) {
    unsigned v;
    asm volatile("ld.acquire.gpu.global.u32 %0, [%1];" : "=r"(v) : "l"(p) : "memory");
    return v;
}

// ---------------- scratch (__device__ globals; no allocation APIs) ----------
__device__ float d_gx[(size_t)2 * NT * NGATE * NB];     // [dir][t][gate][b]
__device__ float d_hs[(size_t)2 * NT * NH * NB];        // [dir][t][j][b]
__device__ float d_feats[(size_t)NB * NT * 2 * NH];     // [b][t][2H]
__device__ float d_em[(size_t)NB * NT * NK];            // [b][t][k]
__device__ int d_preds[NB * NT];
__device__ float d_loss_partial[NB];
__device__ float d_loss;
__device__ unsigned int d_bar2[64];                     // [dir*32]: 128B apart

__global__ void k_init() {
    if (threadIdx.x < 64) d_bar2[threadIdx.x] = 0u;
}

// ---------------- input projection: gx[dir][t][g][b] = W_ih[g]·emb + b ------
__global__ __launch_bounds__(256) void k_gx(
    const int* __restrict__ widx, const int* __restrict__ lens,
    const float* __restrict__ wvec,
    const float* __restrict__ Wih_f, const float* __restrict__ b_f,
    const float* __restrict__ Wih_b, const float* __restrict__ b_b)
{
    __shared__ float4 sWd[64 * 32];       // [row-pair][col] dup: (w0,w0,w1,w1)
    __shared__ float sXT[32 * 66];        // [e][b]
    __shared__ int rowidx[64];
    const int t = blockIdx.y;
    const int dir = blockIdx.z;
    const int g0 = blockIdx.x * 128;
    const float* Wih = dir ? Wih_b : Wih_f;
    const float* bias = dir ? b_b : b_f;
    const int tid = threadIdx.x;
    if (tid < 64) {
        int len = lens[tid];
        int tt = t;
        if (dir) tt = (t < len) ? (len - 1 - t) : t;  // reversed sequence
        rowidx[tid] = widx[tid * NT + tt];            // fused embedding gather
    }
    const int bg = tid & 15;   // batch group (4 batches)
    const int gg = tid >> 4;   // gate-row group (8 rows)
    u64 acc[8][2];
#pragma unroll
    for (int u = 0; u < 8; u++) {
        float bv = bias[g0 + gg * 8 + u];
        acc[u][0] = pk2(bv, bv);
        acc[u][1] = acc[u][0];
    }
    for (int e0 = 0; e0 < NE; e0 += 32) {
        __syncthreads();
#pragma unroll
        for (int i = 0; i < 16; i++) {            // W slice, duplicated pairs
            int idx = tid + i * 256;
            int r = idx >> 5, c = idx & 31;
            float w = Wih[(size_t)(g0 + r) * NE + e0 + c];
            float* dst = (float*)&sWd[(r >> 1) * 32 + c];
            dst[(r & 1) * 2 + 0] = w;
            dst[(r & 1) * 2 + 1] = w;
        }
#pragma unroll
        for (int i = 0; i < 8; i++) {             // X transposed [e][b]
            int idx = tid + i * 256;
            int r = idx >> 5, c = idx & 31;
            sXT[c * 66 + r] = wvec[(size_t)rowidx[r] * NE + e0 + c];
        }
        __syncthreads();
#pragma unroll
        for (int kk = 0; kk < 32; kk++) {
            u64 x01 = *(const u64*)&sXT[kk * 66 + bg * 4];
            u64 x23 = *(const u64*)&sXT[kk * 66 + bg * 4 + 2];
#pragma unroll
            for (int up = 0; up < 4; up++) {
                ulonglong2 wq = *(const ulonglong2*)&sWd[(gg * 4 + up) * 32 + kk];
                fma2(acc[up * 2 + 0][0], wq.x, x01);
                fma2(acc[up * 2 + 0][1], wq.x, x23);
                fma2(acc[up * 2 + 1][0], wq.y, x01);
                fma2(acc[up * 2 + 1][1], wq.y, x23);
            }
        }
    }
    float* gout = d_gx + ((size_t)(dir * NT + t) * NGATE + g0) * NB;
#pragma unroll
    for (int u = 0; u < 8; u++) {
        *(u64*)(gout + (gg * 8 + u) * NB + bg * 4) = acc[u][0];
        *(u64*)(gout + (gg * 8 + u) * NB + bg * 4 + 2) = acc[u][1];
    }
}

// ---------------- persistent bidirectional LSTM recurrence ------------------
// 128 CTAs (64/dir), 256 threads. One release/acquire barrier per step.
// ks = tid>>6 owns k-range [ks*64, ks*64+64); within a 64-thread quarter,
// rg = (tid&63)>>4 owns gate rg (4 unit-rows), bp = tid&15 owns 4 batches.
// cp.async group discipline (per thread, uniform every step):
//   commit h(t-1) tile | commit gx(t+1) | CP_WAIT(1) | __syncthreads
//   -> gx(t) and the whole h tile are complete AND visible; gx(t+1) in flight.
// smem floats: WsP 8192 | h 16384 | sgx 2048 | gpart 4096 = 30720 (120KB)
#define LSTM_SMEM_FLOATS (8192 + 16384 + 2048 + 4096)
__global__ __launch_bounds__(256, 1) void k_lstm(
    const float* __restrict__ Whh_f, const float* __restrict__ Whh_b)
{
    extern __shared__ float smem[];
    float* WsPf = smem;                        // float4[rg*512 + k*2 + j]
    float* h_sm = smem + 8192;                 // [k=256][b=64]
    float* sgx = smem + 8192 + 16384;          // [2][16 rows][64 b]
    float* gpart = smem + 8192 + 16384 + 2048; // [4 ks][16 rows][64 b]
    const int tid = threadIdx.x;
    const int dir = blockIdx.x >> 6;
    const int p = blockIdx.x & 63;
    const int j0 = p * 4;                      // 4 hidden units per CTA
    const float* Whh = dir ? Whh_b : Whh_f;
    // W_hh slice: rows (gate rg, units j0..j0+3), duplicated pairs for f32x2
#pragma unroll
    for (int i = 0; i < 8; i++) {
        int idx = tid + i * 256;               // 2048 float4 entries
        int j = idx & 1, k = (idx >> 1) & 255, rg = idx >> 9;
        float w0 = Whh[(size_t)(rg * NH + j0 + j * 2 + 0) * NH + k];
        float w1 = Whh[(size_t)(rg * NH + j0 + j * 2 + 1) * NH + k];
        ((float4*)WsPf)[idx] = make_float4(w0, w0, w1, w1);
    }
    const int tl = tid & 63;
    const int ks = tid >> 6;                   // k-range owner (0..3)
    const int rg = tl >> 4;                    // gate group (4 unit-rows)
    const int bp = tl & 15;                    // batch quad
    const int fu = tid >> 6;                   // finalize unit (tid<128 only)
    const int bA = tid & 63;
    float cA = 0.f, cB = 0.f;
    unsigned target = 0u;
    unsigned* bar = &d_bar2[dir * 32];
    const unsigned h_b32 = smem_u32(h_sm);
    const unsigned sgx_b32 = smem_u32(sgx);
    const ulonglong2* wpt = (const ulonglong2*)WsPf + rg * 512;
    const int grow = ((tid >> 4) & 15) * 0;    // (placeholder, unused)
    __syncthreads();
    // prologue: prefetch gx(0) into sgx[0] (one group, stays pending)
    {
        const float* gsrc = d_gx + (size_t)(dir * NT) * NGATE * NB;
        int row = tid >> 4, fc = tid & 15;
        int gr = (row >> 2) * NH + j0 + (row & 3);
        cp16(sgx_b32 + (row * 64 + fc * 4) * 4,
             gsrc + (size_t)gr * NB + fc * 4);
        cp_commit();
    }
    for (int t = 0; t < NT; t++) {
        if (t > 0) {                           // wait for h(t-1) from all CTAs
            target += 64u;
            if (tid == 0) {
                while (ld_acquire(bar) < target) {}
            }
            __syncthreads();                   // SYNC A
        }
        // group 1: full h(t-1) tile (4096 float4, 16 per thread); empty at t=0
        if (t > 0) {
            const float* hsrc = d_hs + (size_t)(dir * NT + t - 1) * NH * NB;
#pragma unroll
            for (int i = 0; i < 16; i++) {
                int idx = tid + i * 256;
                int k = idx >> 4, fc = idx & 15;
                cp16(h_b32 + (k * 64 + fc * 4) * 4,
                     hsrc + (size_t)k * NB + fc * 4);
            }
        }
        cp_commit();
        // group 2: gx(t+1) prefetch (1 float4/thread); empty at last step
        if (t + 1 < NT) {
            const float* gsrc = d_gx + (size_t)(dir * NT + t + 1) * NGATE * NB;
            int row = tid >> 4, fc = tid & 15;
            int gr = (row >> 2) * NH + j0 + (row & 3);
            cp16(sgx_b32 + (((t + 1) & 1) * 1024 + row * 64 + fc * 4) * 4,
                 gsrc + (size_t)gr * NB + fc * 4);
        }
        cp_commit();
        CP_WAIT(1);                            // gx(t) + h tile done (own copies)
        __syncthreads();                       // SYNC B: publish to all threads
        const float* gx_s = sgx + (t & 1) * 1024;
        u64 A[4][2];
        if (ks == 0) {
#pragma unroll
            for (int u = 0; u < 4; u++) {
                A[u][0] = *(const u64*)(gx_s + (rg * 4 + u) * 64 + bp * 4);
                A[u][1] = *(const u64*)(gx_s + (rg * 4 + u) * 64 + bp * 4 + 2);
            }
        } else {
#pragma unroll
            for (int u = 0; u < 4; u++) { A[u][0] = 0ull; A[u][1] = 0ull; }
        }
        if (t > 0) {
            const int kb = ks * 64;
#pragma unroll 16
            for (int k = kb; k < kb + 64; k++) {
                ulonglong2 wa = wpt[k * 2];
                ulonglong2 wb = wpt[k * 2 + 1];
                ulonglong2 hq = *(const ulonglong2*)(h_sm + k * 64 + bp * 4);
                fma2(A[0][0], wa.x, hq.x); fma2(A[0][1], wa.x, hq.y);
                fma2(A[1][0], wa.y, hq.x); fma2(A[1][1], wa.y, hq.y);
                fma2(A[2][0], wb.x, hq.x); fma2(A[2][1], wb.x, hq.y);
                fma2(A[3][0], wb.y, hq.x); fma2(A[3][1], wb.y, hq.y);
            }
        }
        // store partial sums
#pragma unroll
        for (int u = 0; u < 4; u++) {
            *(u64*)(gpart + ks * 1024 + (rg * 4 + u) * 64 + bp * 4) = A[u][0];
            *(u64*)(gpart + ks * 1024 + (rg * 4 + u) * 64 + bp * 4 + 2) = A[u][1];
        }
        __syncthreads();                       // SYNC C: gpart complete
        // finalize: tid<128, unit u0 = tid>>6 (0/1) and u0+2, batch bA
        if (tid < 128) {
            float* hout = d_hs + (size_t)((dir * NT + t) * NH + j0) * NB;
            int u0 = fu;
            {
                float gi = 0.f, gf = 0.f, gc = 0.f, go = 0.f;
#pragma unroll
                for (int s = 0; s < 4; s++) {
                    const float* gp = gpart + s * 1024;
                    gi += gp[(0 + u0) * 64 + bA];
                    gf += gp[(4 + u0) * 64 + bA];
                    gc += gp[(8 + u0) * 64 + bA];
                    go += gp[(12 + u0) * 64 + bA];
                }
                float si = 1.f / (1.f + __expf(-gi));
                float sf = 1.f / (1.f + __expf(-gf));
                float so = 1.f / (1.f + __expf(-go));
                cA = sf * cA + si * tanhf(gc);
                hout[u0 * NB + bA] = so * tanhf(cA);
            }
            {
                int u2 = u0 + 2;
                float gi = 0.f, gf = 0.f, gc = 0.f, go = 0.f;
#pragma unroll
                for (int s = 0; s < 4; s++) {
                    const float* gp = gpart + s * 1024;
                    gi += gp[(0 + u2) * 64 + bA];
                    gf += gp[(4 + u2) * 64 + bA];
                    gc += gp[(8 + u2) * 64 + bA];
                    go += gp[(12 + u2) * 64 + bA];
                }
                float si = 1.f / (1.f + __expf(-gi));
                float sf = 1.f / (1.f + __expf(-gf));
                float so = 1.f / (1.f + __expf(-go));
                cB = sf * cB + si * tanhf(gc);
                hout[u2 * NB + bA] = so * tanhf(cB);
            }
        }
        __syncthreads();                       // SYNC D: h(t) stores issued
        if (tid == 0) red_release(bar);        // release: h(t) visible
    }
}

// ---------------- feats: [b][t][2H] = mask * [h_fwd | h_bwd(unreversed)] ----
__global__ __launch_bounds__(256) void k_feats(const int* __restrict__ lens)
{
    __shared__ float tile[64][65];
    __shared__ int slen[64];
    const int ts = blockIdx.x;          // SOURCE time (keeps writes coalesced)
    const int j0 = blockIdx.y * 64;
    const int dir = blockIdx.z;
    const int tid = threadIdx.x;
    if (tid < 64) slen[tid] = lens[tid];
    const int b = tid & 63, jl = tid >> 6;
    const float* hsrc = d_hs + (size_t)((dir * NT + ts) * NH + j0) * NB;
#pragma unroll
    for (int i = 0; i < 16; i++)
        tile[jl + i * 4][b] = hsrc[(jl + i * 4) * NB + b];
    __syncthreads();
    const int jj = tid & 63, br = tid >> 6;
#pragma unroll
    for (int i = 0; i < 16; i++) {
        int bb = br * 16 + i;
        int len = slen[bb];
        bool valid = ts < len;
        int tout = dir ? (valid ? (len - 1 - ts) : ts) : ts;
        float v = valid ? tile[jj][bb] : 0.f;
        d_feats[(size_t)(bb * NT + tout) * (2 * NH) + dir * NH + j0 + jj] = v;
    }
}

// ---------------- emissions = feats @ W_out^T + b_out -----------------------
__global__ __launch_bounds__(256) void k_emis(const float* __restrict__ Wout,
                                              const float* __restrict__ bout)
{
    __shared__ float sW[NK * 512];
    const int tid = threadIdx.x;
    for (int i = tid; i < NK * 512; i += 256) sW[i] = Wout[i];
    __syncthreads();
    const int lane = tid & 31, warp = tid >> 5;
    const size_t bt = (size_t)blockIdx.x * 8 + warp;
    const float* f = d_feats + bt * 512;
    float x[16];
#pragma unroll
    for (int i = 0; i < 16; i++) x[i] = f[lane + i * 32];
#pragma unroll
    for (int k = 0; k < NK; k++) {
        float acc = 0.f;
#pragma unroll
        for (int i = 0; i < 16; i++) acc += x[i] * sW[k * 512 + lane + i * 32];
#pragma unroll
        for (int off = 16; off; off >>= 1)
            acc += __shfl_xor_sync(0xffffffffu, acc, off);
        if (lane == 0) d_em[bt * NK + k] = acc + bout[k];
    }
}

// ---------------- CRF: numerator + alpha (logZ) + Viterbi + backtrace -------
__global__ void k_crf(const int* __restrict__ lens, const int* __restrict__ labels,
                      const float* __restrict__ stt, const float* __restrict__ ett,
                      const float* __restrict__ trans)
{
    __shared__ unsigned char hist[NT][NK];
    const int b = blockIdx.x;
    const int lane = threadIdx.x;
    const int len = lens[b];
    const float* em = d_em + (size_t)b * NT * NK;
    const int* lab = labels + b * NT;
    const int j = (lane < NK) ? lane : 0;
    float tr[NK];
#pragma unroll
    for (int i = 0; i < NK; i++) tr[i] = trans[i * NK + j];
    float sA = stt[j] + em[j];
    float sV = sA;
    int yprev = lab[0];
    float num = stt[yprev] + em[yprev];
    for (int t = 1; t < NT; t++) {
        float e = em[t * NK + j];
        bool m = t < len;
        float aA[NK], aV[NK];
#pragma unroll
        for (int i = 0; i < NK; i++) {
            aA[i] = __shfl_sync(0xffffffffu, sA, i) + tr[i];
            aV[i] = __shfl_sync(0xffffffffu, sV, i) + tr[i];
        }
        float mA = aA[0];
#pragma unroll
        for (int i = 1; i < NK; i++) mA = fmaxf(mA, aA[i]);
        float ssum = 0.f;
#pragma unroll
        for (int i = 0; i < NK; i++) ssum += __expf(aA[i] - mA);
        float nA = mA + __logf(ssum) + e;
        float mV = aV[0]; int bp = 0;
#pragma unroll
        for (int i = 1; i < NK; i++) { if (aV[i] > mV) { mV = aV[i]; bp = i; } }
        float nV = mV + e;
        if (lane < NK) hist[t][lane] = (unsigned char)bp;
        if (m) { sA = nA; sV = nV; }
        if (lane == 0) {
            int y = lab[t];
            if (m) num += trans[yprev * NK + y] + em[t * NK + y];
            yprev = y;
        }
    }
    float fA = sA + ett[j];
    float fV = sV + ett[j];
    float gA[NK], gV[NK];
#pragma unroll
    for (int i = 0; i < NK; i++) {
        gA[i] = __shfl_sync(0xffffffffu, fA, i);
        gV[i] = __shfl_sync(0xffffffffu, fV, i);
    }
    __syncwarp();
    if (lane == 0) {
        float mA = gA[0];
#pragma unroll
        for (int i = 1; i < NK; i++) mA = fmaxf(mA, gA[i]);
        float ssum = 0.f;
#pragma unroll
        for (int i = 0; i < NK; i++) ssum += __expf(gA[i] - mA);
        float denom = mA + __logf(ssum);
        int bl = 0; float mV = gV[0];
#pragma unroll
        for (int i = 1; i < NK; i++) { if (gV[i] > mV) { mV = gV[i]; bl = i; } }
        num += ett[lab[len - 1]];
        d_loss_partial[b] = num - denom;
        int cur = bl;
        d_preds[b * NT + NT - 1] = (NT - 1 < len) ? cur : 0;
        for (int t = NT - 2; t >= 0; t--) {
            if (t + 1 < len) cur = (int)hist[t + 1][cur];
            d_preds[b * NT + t] = (t < len) ? cur : 0;
        }
    }
}

__global__ void k_loss() {
    float s = 0.f;
    for (int i = 0; i < NB; i++) s += d_loss_partial[i];
    d_loss = -s / (float)NB;
}

// output layout: [loss(1), preds(B*T), feats(B*T*2H)] as float32, prefix-safe.
__global__ void k_writeout(float* __restrict__ out, int n) {
    int i = blockIdx.x * 256 + threadIdx.x;
    if (i >= n) return;
    float v = 0.f;
    if (i == 0) v = d_loss;
    else if (i < 1 + NB * NT) v = (float)d_preds[i - 1];
    else if (i < 1 + NB * NT + NB * NT * 2 * NH) v = d_feats[i - 1 - NB * NT];
    out[i] = v;
}

extern "C" void kernel_launch(void* const* d_in, const int* in_sizes, int n_in,
                              void* d_out, int out_size) {
    const int* widx = (const int*)d_in[0];
    const int* lens = (const int*)d_in[1];
    const int* labels = (const int*)d_in[2];
    const float* wvec = (const float*)d_in[3];
    const float* Wih_f = (const float*)d_in[4];
    const float* Whh_f = (const float*)d_in[5];
    const float* b_f = (const float*)d_in[6];
    const float* Wih_b = (const float*)d_in[7];
    const float* Whh_b = (const float*)d_in[8];
    const float* b_b = (const float*)d_in[9];
    const float* Wout = (const float*)d_in[10];
    const float* bout = (const float*)d_in[11];
    const float* stt = (const float*)d_in[12];
    const float* ett = (const float*)d_in[13];
    const float* trans = (const float*)d_in[14];

    k_init<<<1, 64>>>();

    dim3 gg(NGATE / 128, NT, 2);
    k_gx<<<gg, 256>>>(widx, lens, wvec, Wih_f, b_f, Wih_b, b_b);

    int smem_bytes = LSTM_SMEM_FLOATS * 4;
    cudaFuncSetAttribute(k_lstm, cudaFuncAttributeMaxDynamicSharedMemorySize,
                         smem_bytes);
    k_lstm<<<NCTA, 256, smem_bytes>>>(Whh_f, Whh_b);

    dim3 gf(NT, NH / 64, 2);
    k_feats<<<gf, 256>>>(lens);

    k_emis<<<NB * NT / 8, 256>>>(Wout, bout);
    k_crf<<<NB, 32>>>(lens, labels, stt, ett, trans);
    k_loss<<<1, 1>>>();

    k_writeout<<<(out_size + 255) / 256, 256>>>((float*)d_out, out_size);
}

// round 7
// speedup vs baseline: 1.8192x; 1.3437x over previous
#include <cuda_runtime.h>

#define NB 64       // batch
#define NT 512      // seq len
#define NE 256      // embed dim
#define NH 256      // hidden
#define NGATE 1024  // 4*NH
#define NK 9        // tags
#define NCTA 128    // persistent LSTM grid (64 per direction)

typedef unsigned long long u64;

// ---------------- packed fp32x2 helpers (sm_103a FFMA2) ---------------------
__device__ __forceinline__ void fma2(u64& d, u64 a, u64 b) {
    asm("fma.rn.f32x2 %0, %1, %2, %0;" : "+l"(d) : "l"(a), "l"(b));
}
__device__ __forceinline__ u64 pk2(float x, float y) {
    u64 r; asm("mov.b64 %0, {%1,%2};" : "=l"(r) : "f"(x), "f"(y)); return r;
}
__device__ __forceinline__ unsigned smem_u32(const void* p) {
    return (unsigned)__cvta_generic_to_shared(p);
}
__device__ __forceinline__ void cp16(unsigned dst, const void* src) {
    asm volatile("cp.async.cg.shared.global [%0], [%1], 16;" :: "r"(dst), "l"(src));
}
__device__ __forceinline__ void cp_commit() {
    asm volatile("cp.async.commit_group;");
}
#define CP_WAIT(n) asm volatile("cp.async.wait_group %0;" :: "n"(n))
__device__ __forceinline__ void red_release(unsigned* p) {
    asm volatile("red.release.gpu.global.add.u32 [%0], 1;" :: "l"(p) : "memory");
}
__device__ __forceinline__ unsigned ld_acquire(const unsigned* p) {
    unsigned v;
    asm volatile("ld.acquire.gpu.global.u32 %0, [%1];" : "=r"(v) : "l"(p) : "memory");
    return v;
}

// ---------------- scratch (__device__ globals; no allocation APIs) ----------
__device__ float d_gx[(size_t)2 * NT * NGATE * NB];     // [dir][t][gate][b]
__device__ float d_hs[(size_t)2 * NT * NH * NB];        // [dir][t][j][b]
__device__ float d_feats[(size_t)NB * NT * 2 * NH];     // [b][t][2H]
__device__ float d_em[(size_t)NB * NT * NK];            // [b][t][k]
__device__ int d_preds[NB * NT];
__device__ float d_loss_partial[NB];
__device__ float d_loss;
__device__ unsigned d_flagA[2 * 64];   // per-CTA step flags, contiguous per dir

__global__ void k_init() {
    if (threadIdx.x < 128) d_flagA[threadIdx.x] = 0u;
}

// no-op launch: pads the launch sequence so ncu's profiled slot (#3) = k_lstm
__global__ void k_nop() {}

// ---------------- input projection: gx[dir][t][g][b] = W_ih[g]·emb + b ------
__global__ __launch_bounds__(256) void k_gx(
    const int* __restrict__ widx, const int* __restrict__ lens,
    const float* __restrict__ wvec,
    const float* __restrict__ Wih_f, const float* __restrict__ b_f,
    const float* __restrict__ Wih_b, const float* __restrict__ b_b)
{
    __shared__ float4 sWd[64 * 32];       // [row-pair][col] dup: (w0,w0,w1,w1)
    __shared__ float sXT[32 * 66];        // [e][b]
    __shared__ int rowidx[64];
    const int t = blockIdx.y;
    const int dir = blockIdx.z;
    const int g0 = blockIdx.x * 128;
    const float* Wih = dir ? Wih_b : Wih_f;
    const float* bias = dir ? b_b : b_f;
    const int tid = threadIdx.x;
    if (tid < 64) {
        int len = lens[tid];
        int tt = t;
        if (dir) tt = (t < len) ? (len - 1 - t) : t;  // reversed sequence
        rowidx[tid] = widx[tid * NT + tt];            // fused embedding gather
    }
    const int bg = tid & 15;   // batch group (4 batches)
    const int gg = tid >> 4;   // gate-row group (8 rows)
    u64 acc[8][2];
#pragma unroll
    for (int u = 0; u < 8; u++) {
        float bv = bias[g0 + gg * 8 + u];
        acc[u][0] = pk2(bv, bv);
        acc[u][1] = acc[u][0];
    }
    for (int e0 = 0; e0 < NE; e0 += 32) {
        __syncthreads();
#pragma unroll
        for (int i = 0; i < 16; i++) {            // W slice, duplicated pairs
            int idx = tid + i * 256;
            int r = idx >> 5, c = idx & 31;
            float w = Wih[(size_t)(g0 + r) * NE + e0 + c];
            float* dst = (float*)&sWd[(r >> 1) * 32 + c];
            dst[(r & 1) * 2 + 0] = w;
            dst[(r & 1) * 2 + 1] = w;
        }
#pragma unroll
        for (int i = 0; i < 8; i++) {             // X transposed [e][b]
            int idx = tid + i * 256;
            int r = idx >> 5, c = idx & 31;
            sXT[c * 66 + r] = wvec[(size_t)rowidx[r] * NE + e0 + c];
        }
        __syncthreads();
#pragma unroll
        for (int kk = 0; kk < 32; kk++) {
            u64 x01 = *(const u64*)&sXT[kk * 66 + bg * 4];
            u64 x23 = *(const u64*)&sXT[kk * 66 + bg * 4 + 2];
#pragma unroll
            for (int up = 0; up < 4; up++) {
                ulonglong2 wq = *(const ulonglong2*)&sWd[(gg * 4 + up) * 32 + kk];
                fma2(acc[up * 2 + 0][0], wq.x, x01);
                fma2(acc[up * 2 + 0][1], wq.x, x23);
                fma2(acc[up * 2 + 1][0], wq.y, x01);
                fma2(acc[up * 2 + 1][1], wq.y, x23);
            }
        }
    }
    float* gout = d_gx + ((size_t)(dir * NT + t) * NGATE + g0) * NB;
#pragma unroll
    for (int u = 0; u < 8; u++) {
        *(u64*)(gout + (gg * 8 + u) * NB + bg * 4) = acc[u][0];
        *(u64*)(gout + (gg * 8 + u) * NB + bg * 4 + 2) = acc[u][1];
    }
}

// ---------------- persistent bidirectional LSTM recurrence ------------------
// 128 CTAs (64/dir), 128 threads. Per-CTA flag slots (release/acquire), gx
// prefetched one step ahead into smem, h tile loaded in 4 overlapped chunks.
// cp.async group order per step: [h0][h1][h2][h3][gx(t+1)]; CP_WAIT(4..1)
// with __syncthreads after each wait (cross-thread smem visibility).
// smem floats: WsP 8192 | h 16384 | sgx 2048 | g_sm 1024 = 27648 (108 KB)
#define LSTM_SMEM_FLOATS (8192 + 16384 + 2048 + 1024)
__global__ __launch_bounds__(128, 1) void k_lstm(
    const float* __restrict__ Whh_f, const float* __restrict__ Whh_b)
{
    extern __shared__ float smem[];
    float* WsPf = smem;                        // float4[8 rp][256 k] dup pairs
    float* h_sm = smem + 8192;                 // [k=256][b=64]
    float* sgx = smem + 8192 + 16384;          // [2][16 rows][64 b]
    float* g_sm = smem + 8192 + 16384 + 2048;  // [16 rows][64 b]
    const int tid = threadIdx.x;
    const int dir = blockIdx.x >> 6;
    const int p = blockIdx.x & 63;
    const int j0 = p * 4;                      // 4 hidden units per CTA
    const float* Whh = dir ? Whh_b : Whh_f;
#pragma unroll
    for (int i = 0; i < 16; i++) {             // W_hh slice, duplicated pairs
        int idx = tid + i * 128;
        int rp_ = idx >> 8, k = idx & 255;
        int rl0 = rp_ * 2;
        int q = rl0 >> 2, jj = rl0 & 3;
        float w0 = Whh[(size_t)(q * NH + j0 + jj) * NH + k];
        float w1 = Whh[(size_t)(q * NH + j0 + jj + 1) * NH + k];
        ((float4*)WsPf)[rp_ * 256 + k] = make_float4(w0, w0, w1, w1);
    }
    const int bp = tid & 15;                   // batch quad
    const int rp = tid >> 4;                   // row pair (rows 2rp, 2rp+1)
    const int rl0 = rp * 2;
    const int jA = tid >> 6, bA = tid & 63;    // finalize: units jA, jA+2
    float cA = 0.f, cB = 0.f;
    const unsigned h_b32 = smem_u32(h_sm);
    const unsigned sgx_b32 = smem_u32(sgx);
    const ulonglong2* wp = (const ulonglong2*)WsPf + rp * 256;
    __syncthreads();
    // prologue: prefetch gx(0) into sgx[0] (one group)
    {
        const float* gsrc = d_gx + (size_t)(dir * NT) * NGATE * NB;
#pragma unroll
        for (int i = 0; i < 2; i++) {
            int idx = tid + i * 128;           // 256 float4
            int row = idx >> 4, fc = idx & 15;
            int gr = (row >> 2) * NH + j0 + (row & 3);
            cp16(sgx_b32 + (row * 64 + fc * 4) * 4,
                 gsrc + (size_t)gr * NB + fc * 4);
        }
        cp_commit();
    }
    for (int t = 0; t < NT; t++) {
        if (t > 0) {                           // all 64 producer flags >= t
            if (tid < 64) {
                const unsigned* fp = &d_flagA[dir * 64 + tid];
                while (ld_acquire(fp) < (unsigned)t) {}
            }
            __syncthreads();                   // SYNC A
        }
        // groups 1-4: h(t-1) tile in 4 chunks of 64 k (1024 float4 each)
        if (t > 0) {
            const float* hsrc = d_hs + (size_t)(dir * NT + t - 1) * NH * NB;
#pragma unroll
            for (int c = 0; c < 4; c++) {
#pragma unroll
                for (int i = 0; i < 8; i++) {
                    int idx = c * 1024 + i * 128 + tid;
                    int k = idx >> 4, fc = idx & 15;
                    cp16(h_b32 + (k * 64 + fc * 4) * 4,
                         hsrc + (size_t)k * NB + fc * 4);
                }
                cp_commit();
            }
        } else {
            cp_commit(); cp_commit(); cp_commit(); cp_commit();
        }
        // group 5: gx(t+1) prefetch (empty at last step)
        if (t + 1 < NT) {
            const float* gsrc = d_gx + (size_t)(dir * NT + t + 1) * NGATE * NB;
#pragma unroll
            for (int i = 0; i < 2; i++) {
                int idx = tid + i * 128;
                int row = idx >> 4, fc = idx & 15;
                int gr = (row >> 2) * NH + j0 + (row & 3);
                cp16(sgx_b32 + (((t + 1) & 1) * 1024 + row * 64 + fc * 4) * 4,
                     gsrc + (size_t)gr * NB + fc * 4);
            }
        }
        cp_commit();
        CP_WAIT(4);                            // gx(t) + h chunk 0 complete
        __syncthreads();                       // publish to all threads
        const float* gx_s = sgx + (t & 1) * 1024;
        u64 a00 = *(const u64*)(gx_s + rl0 * 64 + bp * 4);
        u64 a01 = *(const u64*)(gx_s + rl0 * 64 + bp * 4 + 2);
        u64 a10 = *(const u64*)(gx_s + (rl0 + 1) * 64 + bp * 4);
        u64 a11 = *(const u64*)(gx_s + (rl0 + 1) * 64 + bp * 4 + 2);
        if (t > 0) {
#pragma unroll
            for (int c = 0; c < 4; c++) {
                if (c == 1) { CP_WAIT(3); __syncthreads(); }
                else if (c == 2) { CP_WAIT(2); __syncthreads(); }
                else if (c == 3) { CP_WAIT(1); __syncthreads(); }
#pragma unroll 16
                for (int k = c * 64; k < c * 64 + 64; k++) {
                    ulonglong2 wq = wp[k];
                    ulonglong2 hq = *(const ulonglong2*)(h_sm + k * 64 + bp * 4);
                    fma2(a00, wq.x, hq.x);
                    fma2(a01, wq.x, hq.y);
                    fma2(a10, wq.y, hq.x);
                    fma2(a11, wq.y, hq.y);
                }
            }
        }
        // gate exchange
        *(u64*)(g_sm + rl0 * 64 + bp * 4) = a00;
        *(u64*)(g_sm + rl0 * 64 + bp * 4 + 2) = a01;
        *(u64*)(g_sm + (rl0 + 1) * 64 + bp * 4) = a10;
        *(u64*)(g_sm + (rl0 + 1) * 64 + bp * 4 + 2) = a11;
        __syncthreads();                       // SYNC gates
        float* hout = d_hs + (size_t)((dir * NT + t) * NH + j0) * NB;
        {
            float gi = g_sm[jA * 64 + bA];
            float gf = g_sm[(4 + jA) * 64 + bA];
            float gc = g_sm[(8 + jA) * 64 + bA];
            float go = g_sm[(12 + jA) * 64 + bA];
            float si = 1.f / (1.f + __expf(-gi));
            float sf = 1.f / (1.f + __expf(-gf));
            float so = 1.f / (1.f + __expf(-go));
            cA = sf * cA + si * tanhf(gc);
            hout[jA * NB + bA] = so * tanhf(cA);
        }
        {
            int j2 = jA + 2;
            float gi = g_sm[j2 * 64 + bA];
            float gf = g_sm[(4 + j2) * 64 + bA];
            float gc = g_sm[(8 + j2) * 64 + bA];
            float go = g_sm[(12 + j2) * 64 + bA];
            float si = 1.f / (1.f + __expf(-gi));
            float sf = 1.f / (1.f + __expf(-gf));
            float so = 1.f / (1.f + __expf(-go));
            cB = sf * cB + si * tanhf(gc);
            hout[j2 * NB + bA] = so * tanhf(cB);
        }
        __syncthreads();                       // SYNC h-stores issued
        if (tid == 0) red_release(&d_flagA[dir * 64 + p]);  // own slot
    }
}

// ---------------- feats: [b][t][2H] = mask * [h_fwd | h_bwd(unreversed)] ----
__global__ __launch_bounds__(256) void k_feats(const int* __restrict__ lens)
{
    __shared__ float tile[64][65];
    __shared__ int slen[64];
    const int ts = blockIdx.x;          // SOURCE time (keeps writes coalesced)
    const int j0 = blockIdx.y * 64;
    const int dir = blockIdx.z;
    const int tid = threadIdx.x;
    if (tid < 64) slen[tid] = lens[tid];
    const int b = tid & 63, jl = tid >> 6;
    const float* hsrc = d_hs + (size_t)((dir * NT + ts) * NH + j0) * NB;
#pragma unroll
    for (int i = 0; i < 16; i++)
        tile[jl + i * 4][b] = hsrc[(jl + i * 4) * NB + b];
    __syncthreads();
    const int jj = tid & 63, br = tid >> 6;
#pragma unroll
    for (int i = 0; i < 16; i++) {
        int bb = br * 16 + i;
        int len = slen[bb];
        bool valid = ts < len;
        int tout = dir ? (valid ? (len - 1 - ts) : ts) : ts;
        float v = valid ? tile[jj][bb] : 0.f;
        d_feats[(size_t)(bb * NT + tout) * (2 * NH) + dir * NH + j0 + jj] = v;
    }
}

// ---------------- emissions = feats @ W_out^T + b_out -----------------------
__global__ __launch_bounds__(256) void k_emis(const float* __restrict__ Wout,
                                              const float* __restrict__ bout)
{
    __shared__ float sW[NK * 512];
    const int tid = threadIdx.x;
    for (int i = tid; i < NK * 512; i += 256) sW[i] = Wout[i];
    __syncthreads();
    const int lane = tid & 31, warp = tid >> 5;
    const size_t bt = (size_t)blockIdx.x * 8 + warp;
    const float* f = d_feats + bt * 512;
    float x[16];
#pragma unroll
    for (int i = 0; i < 16; i++) x[i] = f[lane + i * 32];
#pragma unroll
    for (int k = 0; k < NK; k++) {
        float acc = 0.f;
#pragma unroll
        for (int i = 0; i < 16; i++) acc += x[i] * sW[k * 512 + lane + i * 32];
#pragma unroll
        for (int off = 16; off; off >>= 1)
            acc += __shfl_xor_sync(0xffffffffu, acc, off);
        if (lane == 0) d_em[bt * NK + k] = acc + bout[k];
    }
}

// ---------------- CRF: numerator + alpha (logZ) + Viterbi + backtrace -------
__global__ void k_crf(const int* __restrict__ lens, const int* __restrict__ labels,
                      const float* __restrict__ stt, const float* __restrict__ ett,
                      const float* __restrict__ trans)
{
    __shared__ unsigned char hist[NT][NK];
    const int b = blockIdx.x;
    const int lane = threadIdx.x;
    const int len = lens[b];
    const float* em = d_em + (size_t)b * NT * NK;
    const int* lab = labels + b * NT;
    const int j = (lane < NK) ? lane : 0;
    float tr[NK];
#pragma unroll
    for (int i = 0; i < NK; i++) tr[i] = trans[i * NK + j];
    float sA = stt[j] + em[j];
    float sV = sA;
    int yprev = lab[0];
    float num = stt[yprev] + em[yprev];
    for (int t = 1; t < NT; t++) {
        float e = em[t * NK + j];
        bool m = t < len;
        float aA[NK], aV[NK];
#pragma unroll
        for (int i = 0; i < NK; i++) {
            aA[i] = __shfl_sync(0xffffffffu, sA, i) + tr[i];
            aV[i] = __shfl_sync(0xffffffffu, sV, i) + tr[i];
        }
        float mA = aA[0];
#pragma unroll
        for (int i = 1; i < NK; i++) mA = fmaxf(mA, aA[i]);
        float ssum = 0.f;
#pragma unroll
        for (int i = 0; i < NK; i++) ssum += __expf(aA[i] - mA);
        float nA = mA + __logf(ssum) + e;
        float mV = aV[0]; int bp = 0;
#pragma unroll
        for (int i = 1; i < NK; i++) { if (aV[i] > mV) { mV = aV[i]; bp = i; } }
        float nV = mV + e;
        if (lane < NK) hist[t][lane] = (unsigned char)bp;
        if (m) { sA = nA; sV = nV; }
        if (lane == 0) {
            int y = lab[t];
            if (m) num += trans[yprev * NK + y] + em[t * NK + y];
            yprev = y;
        }
    }
    float fA = sA + ett[j];
    float fV = sV + ett[j];
    float gA[NK], gV[NK];
#pragma unroll
    for (int i = 0; i < NK; i++) {
        gA[i] = __shfl_sync(0xffffffffu, fA, i);
        gV[i] = __shfl_sync(0xffffffffu, fV, i);
    }
    __syncwarp();
    if (lane == 0) {
        float mA = gA[0];
#pragma unroll
        for (int i = 1; i < NK; i++) mA = fmaxf(mA, gA[i]);
        float ssum = 0.f;
#pragma unroll
        for (int i = 0; i < NK; i++) ssum += __expf(gA[i] - mA);
        float denom = mA + __logf(ssum);
        int bl = 0; float mV = gV[0];
#pragma unroll
        for (int i = 1; i < NK; i++) { if (gV[i] > mV) { mV = gV[i]; bl = i; } }
        num += ett[lab[len - 1]];
        d_loss_partial[b] = num - denom;
        int cur = bl;
        d_preds[b * NT + NT - 1] = (NT - 1 < len) ? cur : 0;
        for (int t = NT - 2; t >= 0; t--) {
            if (t + 1 < len) cur = (int)hist[t + 1][cur];
            d_preds[b * NT + t] = (t < len) ? cur : 0;
        }
    }
}

__global__ void k_loss() {
    float s = 0.f;
    for (int i = 0; i < NB; i++) s += d_loss_partial[i];
    d_loss = -s / (float)NB;
}

// output layout: [loss(1), preds(B*T), feats(B*T*2H)] as float32, prefix-safe.
__global__ void k_writeout(float* __restrict__ out, int n) {
    int i = blockIdx.x * 256 + threadIdx.x;
    if (i >= n) return;
    float v = 0.f;
    if (i == 0) v = d_loss;
    else if (i < 1 + NB * NT) v = (float)d_preds[i - 1];
    else if (i < 1 + NB * NT + NB * NT * 2 * NH) v = d_feats[i - 1 - NB * NT];
    out[i] = v;
}

extern "C" void kernel_launch(void* const* d_in, const int* in_sizes, int n_in,
                              void* d_out, int out_size) {
    const int* widx = (const int*)d_in[0];
    const int* lens = (const int*)d_in[1];
    const int* labels = (const int*)d_in[2];
    const float* wvec = (const float*)d_in[3];
    const float* Wih_f = (const float*)d_in[4];
    const float* Whh_f = (const float*)d_in[5];
    const float* b_f = (const float*)d_in[6];
    const float* Wih_b = (const float*)d_in[7];
    const float* Whh_b = (const float*)d_in[8];
    const float* b_b = (const float*)d_in[9];
    const float* Wout = (const float*)d_in[10];
    const float* bout = (const float*)d_in[11];
    const float* stt = (const float*)d_in[12];
    const float* ett = (const float*)d_in[13];
    const float* trans = (const float*)d_in[14];

    k_init<<<1, 128>>>();                       // launch 0

    dim3 gg(NGATE / 128, NT, 2);
    k_gx<<<gg, 256>>>(widx, lens, wvec, Wih_f, b_f, Wih_b, b_b);  // launch 1

    k_nop<<<1, 32>>>();                         // launch 2 (pads ncu slot)

    int smem_bytes = LSTM_SMEM_FLOATS * 4;
    cudaFuncSetAttribute(k_lstm, cudaFuncAttributeMaxDynamicSharedMemorySize,
                         smem_bytes);
    k_lstm<<<NCTA, 128, smem_bytes>>>(Whh_f, Whh_b);  // launch 3 <- profiled

    dim3 gf(NT, NH / 64, 2);
    k_feats<<<gf, 256>>>(lens);

    k_emis<<<NB * NT / 8, 256>>>(Wout, bout);
    k_crf<<<NB, 32>>>(lens, labels, stt, ett, trans);
    k_loss<<<1, 1>>>();

    k_writeout<<<(out_size + 255) / 256, 256>>>((float*)d_out, out_size);
}

// round 8
// speedup vs baseline: 1.8247x; 1.0030x over previous
#include <cuda_runtime.h>

#define NB 64       // batch
#define NT 512      // seq len
#define NE 256      // embed dim
#define NH 256      // hidden
#define NGATE 1024  // 4*NH
#define NK 9        // tags
#define NCTA 128    // persistent LSTM grid (64 per direction)

typedef unsigned long long u64;

// ---------------- packed fp32x2 helpers (sm_103a FFMA2) ---------------------
__device__ __forceinline__ void fma2(u64& d, u64 a, u64 b) {
    asm("fma.rn.f32x2 %0, %1, %2, %0;" : "+l"(d) : "l"(a), "l"(b));
}
__device__ __forceinline__ u64 pk2(float x, float y) {
    u64 r; asm("mov.b64 %0, {%1,%2};" : "=l"(r) : "f"(x), "f"(y)); return r;
}
__device__ __forceinline__ unsigned smem_u32(const void* p) {
    return (unsigned)__cvta_generic_to_shared(p);
}
__device__ __forceinline__ void cp16(unsigned dst, const void* src) {
    asm volatile("cp.async.cg.shared.global [%0], [%1], 16;" :: "r"(dst), "l"(src));
}
__device__ __forceinline__ void cp_commit() {
    asm volatile("cp.async.commit_group;");
}
#define CP_WAIT(n) asm volatile("cp.async.wait_group %0;" :: "n"(n))
__device__ __forceinline__ void red_release(unsigned* p) {
    asm volatile("red.release.gpu.global.add.u32 [%0], 1;" :: "l"(p) : "memory");
}
__device__ __forceinline__ unsigned ld_acquire(const unsigned* p) {
    unsigned v;
    asm volatile("ld.acquire.gpu.global.u32 %0, [%1];" : "=r"(v) : "l"(p) : "memory");
    return v;
}

// ---------------- scratch (__device__ globals; no allocation APIs) ----------
__device__ float d_gx[(size_t)2 * NT * NGATE * NB];     // [dir][t][gate][b]
__device__ float d_hs[(size_t)2 * NT * NH * NB];        // [dir][t][j][b]
__device__ float d_feats[(size_t)NB * NT * 2 * NH];     // [b][t][2H]
__device__ float d_em[(size_t)NB * NT * NK];            // [b][t][k]
__device__ int d_preds[NB * NT];
__device__ float d_loss_partial[NB];
__device__ float d_loss;
// per-CTA step flags, ONE PER 128-BYTE LINE (stride 32 u32) so polls spread
// across L2 slices instead of storming 2 lines.
#define FLAG_STRIDE 32
__device__ unsigned d_flagA[2 * 64 * FLAG_STRIDE];

__global__ void k_init() {
    int i = blockIdx.x * 256 + threadIdx.x;
    if (i < 2 * 64 * FLAG_STRIDE) d_flagA[i] = 0u;
}

// no-op launch: pads the launch sequence so ncu's profiled slot (#3) = k_lstm
__global__ void k_nop() {}

// ---------------- input projection: gx[dir][t][g][b] = W_ih[g]·emb + b ------
__global__ __launch_bounds__(256) void k_gx(
    const int* __restrict__ widx, const int* __restrict__ lens,
    const float* __restrict__ wvec,
    const float* __restrict__ Wih_f, const float* __restrict__ b_f,
    const float* __restrict__ Wih_b, const float* __restrict__ b_b)
{
    __shared__ float4 sWd[64 * 32];       // [row-pair][col] dup: (w0,w0,w1,w1)
    __shared__ float sXT[32 * 66];        // [e][b]
    __shared__ int rowidx[64];
    const int t = blockIdx.y;
    const int dir = blockIdx.z;
    const int g0 = blockIdx.x * 128;
    const float* Wih = dir ? Wih_b : Wih_f;
    const float* bias = dir ? b_b : b_f;
    const int tid = threadIdx.x;
    if (tid < 64) {
        int len = lens[tid];
        int tt = t;
        if (dir) tt = (t < len) ? (len - 1 - t) : t;  // reversed sequence
        rowidx[tid] = widx[tid * NT + tt];            // fused embedding gather
    }
    const int bg = tid & 15;   // batch group (4 batches)
    const int gg = tid >> 4;   // gate-row group (8 rows)
    u64 acc[8][2];
#pragma unroll
    for (int u = 0; u < 8; u++) {
        float bv = bias[g0 + gg * 8 + u];
        acc[u][0] = pk2(bv, bv);
        acc[u][1] = acc[u][0];
    }
    for (int e0 = 0; e0 < NE; e0 += 32) {
        __syncthreads();
#pragma unroll
        for (int i = 0; i < 16; i++) {            // W slice, duplicated pairs
            int idx = tid + i * 256;
            int r = idx >> 5, c = idx & 31;
            float w = Wih[(size_t)(g0 + r) * NE + e0 + c];
            float* dst = (float*)&sWd[(r >> 1) * 32 + c];
            dst[(r & 1) * 2 + 0] = w;
            dst[(r & 1) * 2 + 1] = w;
        }
#pragma unroll
        for (int i = 0; i < 8; i++) {             // X transposed [e][b]
            int idx = tid + i * 256;
            int r = idx >> 5, c = idx & 31;
            sXT[c * 66 + r] = wvec[(size_t)rowidx[r] * NE + e0 + c];
        }
        __syncthreads();
#pragma unroll
        for (int kk = 0; kk < 32; kk++) {
            u64 x01 = *(const u64*)&sXT[kk * 66 + bg * 4];
            u64 x23 = *(const u64*)&sXT[kk * 66 + bg * 4 + 2];
#pragma unroll
            for (int up = 0; up < 4; up++) {
                ulonglong2 wq = *(const ulonglong2*)&sWd[(gg * 4 + up) * 32 + kk];
                fma2(acc[up * 2 + 0][0], wq.x, x01);
                fma2(acc[up * 2 + 0][1], wq.x, x23);
                fma2(acc[up * 2 + 1][0], wq.y, x01);
                fma2(acc[up * 2 + 1][1], wq.y, x23);
            }
        }
    }
    float* gout = d_gx + ((size_t)(dir * NT + t) * NGATE + g0) * NB;
#pragma unroll
    for (int u = 0; u < 8; u++) {
        *(u64*)(gout + (gg * 8 + u) * NB + bg * 4) = acc[u][0];
        *(u64*)(gout + (gg * 8 + u) * NB + bg * 4 + 2) = acc[u][1];
    }
}

// ---------------- persistent bidirectional LSTM recurrence ------------------
// 128 CTAs (64/dir), 128 threads. Per-CTA LINE-PADDED flag slots, gx
// prefetched one step ahead into smem, h tile loaded in 4 overlapped chunks.
// cp.async group order per step: [h0][h1][h2][h3][gx(t+1)]; CP_WAIT(4..1)
// with __syncthreads after each wait (cross-thread smem visibility).
// smem floats: WsP 8192 | h 16384 | sgx 2048 | g_sm 1024 = 27648 (108 KB)
#define LSTM_SMEM_FLOATS (8192 + 16384 + 2048 + 1024)
__global__ __launch_bounds__(128, 1) void k_lstm(
    const float* __restrict__ Whh_f, const float* __restrict__ Whh_b)
{
    extern __shared__ float smem[];
    float* WsPf = smem;                        // float4[8 rp][256 k] dup pairs
    float* h_sm = smem + 8192;                 // [k=256][b=64]
    float* sgx = smem + 8192 + 16384;          // [2][16 rows][64 b]
    float* g_sm = smem + 8192 + 16384 + 2048;  // [16 rows][64 b]
    const int tid = threadIdx.x;
    const int dir = blockIdx.x >> 6;
    const int p = blockIdx.x & 63;
    const int j0 = p * 4;                      // 4 hidden units per CTA
    const float* Whh = dir ? Whh_b : Whh_f;
#pragma unroll
    for (int i = 0; i < 16; i++) {             // W_hh slice, duplicated pairs
        int idx = tid + i * 128;
        int rp_ = idx >> 8, k = idx & 255;
        int rl0 = rp_ * 2;
        int q = rl0 >> 2, jj = rl0 & 3;
        float w0 = Whh[(size_t)(q * NH + j0 + jj) * NH + k];
        float w1 = Whh[(size_t)(q * NH + j0 + jj + 1) * NH + k];
        ((float4*)WsPf)[rp_ * 256 + k] = make_float4(w0, w0, w1, w1);
    }
    const int bp = tid & 15;                   // batch quad
    const int rp = tid >> 4;                   // row pair (rows 2rp, 2rp+1)
    const int rl0 = rp * 2;
    const int jA = tid >> 6, bA = tid & 63;    // finalize: units jA, jA+2
    float cA = 0.f, cB = 0.f;
    const unsigned h_b32 = smem_u32(h_sm);
    const unsigned sgx_b32 = smem_u32(sgx);
    const ulonglong2* wp = (const ulonglong2*)WsPf + rp * 256;
    __syncthreads();
    // prologue: prefetch gx(0) into sgx[0] (one group)
    {
        const float* gsrc = d_gx + (size_t)(dir * NT) * NGATE * NB;
#pragma unroll
        for (int i = 0; i < 2; i++) {
            int idx = tid + i * 128;           // 256 float4
            int row = idx >> 4, fc = idx & 15;
            int gr = (row >> 2) * NH + j0 + (row & 3);
            cp16(sgx_b32 + (row * 64 + fc * 4) * 4,
                 gsrc + (size_t)gr * NB + fc * 4);
        }
        cp_commit();
    }
    for (int t = 0; t < NT; t++) {
        if (t > 0) {                           // all 64 producer flags >= t
            if (tid < 64) {
                const unsigned* fp = &d_flagA[(dir * 64 + tid) * FLAG_STRIDE];
                while (ld_acquire(fp) < (unsigned)t) {}
            }
            __syncthreads();                   // SYNC A
        }
        // groups 1-4: h(t-1) tile in 4 chunks of 64 k (1024 float4 each)
        if (t > 0) {
            const float* hsrc = d_hs + (size_t)(dir * NT + t - 1) * NH * NB;
#pragma unroll
            for (int c = 0; c < 4; c++) {
#pragma unroll
                for (int i = 0; i < 8; i++) {
                    int idx = c * 1024 + i * 128 + tid;
                    int k = idx >> 4, fc = idx & 15;
                    cp16(h_b32 + (k * 64 + fc * 4) * 4,
                         hsrc + (size_t)k * NB + fc * 4);
                }
                cp_commit();
            }
        } else {
            cp_commit(); cp_commit(); cp_commit(); cp_commit();
        }
        // group 5: gx(t+1) prefetch (empty at last step)
        if (t + 1 < NT) {
            const float* gsrc = d_gx + (size_t)(dir * NT + t + 1) * NGATE * NB;
#pragma unroll
            for (int i = 0; i < 2; i++) {
                int idx = tid + i * 128;
                int row = idx >> 4, fc = idx & 15;
                int gr = (row >> 2) * NH + j0 + (row & 3);
                cp16(sgx_b32 + (((t + 1) & 1) * 1024 + row * 64 + fc * 4) * 4,
                     gsrc + (size_t)gr * NB + fc * 4);
            }
        }
        cp_commit();
        CP_WAIT(4);                            // gx(t) + h chunk 0 complete
        __syncthreads();                       // publish to all threads
        const float* gx_s = sgx + (t & 1) * 1024;
        u64 a00 = *(const u64*)(gx_s + rl0 * 64 + bp * 4);
        u64 a01 = *(const u64*)(gx_s + rl0 * 64 + bp * 4 + 2);
        u64 a10 = *(const u64*)(gx_s + (rl0 + 1) * 64 + bp * 4);
        u64 a11 = *(const u64*)(gx_s + (rl0 + 1) * 64 + bp * 4 + 2);
        if (t > 0) {
#pragma unroll
            for (int c = 0; c < 4; c++) {
                if (c == 1) { CP_WAIT(3); __syncthreads(); }
                else if (c == 2) { CP_WAIT(2); __syncthreads(); }
                else if (c == 3) { CP_WAIT(1); __syncthreads(); }
#pragma unroll 16
                for (int k = c * 64; k < c * 64 + 64; k++) {
                    ulonglong2 wq = wp[k];
                    ulonglong2 hq = *(const ulonglong2*)(h_sm + k * 64 + bp * 4);
                    fma2(a00, wq.x, hq.x);
                    fma2(a01, wq.x, hq.y);
                    fma2(a10, wq.y, hq.x);
                    fma2(a11, wq.y, hq.y);
                }
            }
        }
        // gate exchange
        *(u64*)(g_sm + rl0 * 64 + bp * 4) = a00;
        *(u64*)(g_sm + rl0 * 64 + bp * 4 + 2) = a01;
        *(u64*)(g_sm + (rl0 + 1) * 64 + bp * 4) = a10;
        *(u64*)(g_sm + (rl0 + 1) * 64 + bp * 4 + 2) = a11;
        __syncthreads();                       // SYNC gates
        float* hout = d_hs + (size_t)((dir * NT + t) * NH + j0) * NB;
        {
            float gi = g_sm[jA * 64 + bA];
            float gf = g_sm[(4 + jA) * 64 + bA];
            float gc = g_sm[(8 + jA) * 64 + bA];
            float go = g_sm[(12 + jA) * 64 + bA];
            float si = 1.f / (1.f + __expf(-gi));
            float sf = 1.f / (1.f + __expf(-gf));
            float so = 1.f / (1.f + __expf(-go));
            cA = sf * cA + si * tanhf(gc);
            hout[jA * NB + bA] = so * tanhf(cA);
        }
        {
            int j2 = jA + 2;
            float gi = g_sm[j2 * 64 + bA];
            float gf = g_sm[(4 + j2) * 64 + bA];
            float gc = g_sm[(8 + j2) * 64 + bA];
            float go = g_sm[(12 + j2) * 64 + bA];
            float si = 1.f / (1.f + __expf(-gi));
            float sf = 1.f / (1.f + __expf(-gf));
            float so = 1.f / (1.f + __expf(-go));
            cB = sf * cB + si * tanhf(cB * 0.f + gc);   // keep exact: tanhf(gc)
            hout[j2 * NB + bA] = so * tanhf(cB);
        }
        __syncthreads();                       // SYNC h-stores issued
        if (tid == 0)
            red_release(&d_flagA[(dir * 64 + p) * FLAG_STRIDE]);  // own line
    }
}

// ---------------- feats: [b][t][2H] = mask * [h_fwd | h_bwd(unreversed)] ----
__global__ __launch_bounds__(256) void k_feats(const int* __restrict__ lens)
{
    __shared__ float tile[64][65];
    __shared__ int slen[64];
    const int ts = blockIdx.x;          // SOURCE time (keeps writes coalesced)
    const int j0 = blockIdx.y * 64;
    const int dir = blockIdx.z;
    const int tid = threadIdx.x;
    if (tid < 64) slen[tid] = lens[tid];
    const int b = tid & 63, jl = tid >> 6;
    const float* hsrc = d_hs + (size_t)((dir * NT + ts) * NH + j0) * NB;
#pragma unroll
    for (int i = 0; i < 16; i++)
        tile[jl + i * 4][b] = hsrc[(jl + i * 4) * NB + b];
    __syncthreads();
    const int jj = tid & 63, br = tid >> 6;
#pragma unroll
    for (int i = 0; i < 16; i++) {
        int bb = br * 16 + i;
        int len = slen[bb];
        bool valid = ts < len;
        int tout = dir ? (valid ? (len - 1 - ts) : ts) : ts;
        float v = valid ? tile[jj][bb] : 0.f;
        d_feats[(size_t)(bb * NT + tout) * (2 * NH) + dir * NH + j0 + jj] = v;
    }
}

// ---------------- emissions = feats @ W_out^T + b_out -----------------------
__global__ __launch_bounds__(256) void k_emis(const float* __restrict__ Wout,
                                              const float* __restrict__ bout)
{
    __shared__ float sW[NK * 512];
    const int tid = threadIdx.x;
    for (int i = tid; i < NK * 512; i += 256) sW[i] = Wout[i];
    __syncthreads();
    const int lane = tid & 31, warp = tid >> 5;
    const size_t bt = (size_t)blockIdx.x * 8 + warp;
    const float* f = d_feats + bt * 512;
    float x[16];
#pragma unroll
    for (int i = 0; i < 16; i++) x[i] = f[lane + i * 32];
#pragma unroll
    for (int k = 0; k < NK; k++) {
        float acc = 0.f;
#pragma unroll
        for (int i = 0; i < 16; i++) acc += x[i] * sW[k * 512 + lane + i * 32];
#pragma unroll
        for (int off = 16; off; off >>= 1)
            acc += __shfl_xor_sync(0xffffffffu, acc, off);
        if (lane == 0) d_em[bt * NK + k] = acc + bout[k];
    }
}

// ---------------- CRF: numerator + alpha (logZ) + Viterbi + backtrace -------
__global__ void k_crf(const int* __restrict__ lens, const int* __restrict__ labels,
                      const float* __restrict__ stt, const float* __restrict__ ett,
                      const float* __restrict__ trans)
{
    __shared__ unsigned char hist[NT][NK];
    const int b = blockIdx.x;
    const int lane = threadIdx.x;
    const int len = lens[b];
    const float* em = d_em + (size_t)b * NT * NK;
    const int* lab = labels + b * NT;
    const int j = (lane < NK) ? lane : 0;
    float tr[NK];
#pragma unroll
    for (int i = 0; i < NK; i++) tr[i] = trans[i * NK + j];
    float sA = stt[j] + em[j];
    float sV = sA;
    int yprev = lab[0];
    float num = stt[yprev] + em[yprev];
    for (int t = 1; t < NT; t++) {
        float e = em[t * NK + j];
        bool m = t < len;
        float aA[NK], aV[NK];
#pragma unroll
        for (int i = 0; i < NK; i++) {
            aA[i] = __shfl_sync(0xffffffffu, sA, i) + tr[i];
            aV[i] = __shfl_sync(0xffffffffu, sV, i) + tr[i];
        }
        float mA = aA[0];
#pragma unroll
        for (int i = 1; i < NK; i++) mA = fmaxf(mA, aA[i]);
        float ssum = 0.f;
#pragma unroll
        for (int i = 0; i < NK; i++) ssum += __expf(aA[i] - mA);
        float nA = mA + __logf(ssum) + e;
        float mV = aV[0]; int bp = 0;
#pragma unroll
        for (int i = 1; i < NK; i++) { if (aV[i] > mV) { mV = aV[i]; bp = i; } }
        float nV = mV + e;
        if (lane < NK) hist[t][lane] = (unsigned char)bp;
        if (m) { sA = nA; sV = nV; }
        if (lane == 0) {
            int y = lab[t];
            if (m) num += trans[yprev * NK + y] + em[t * NK + y];
            yprev = y;
        }
    }
    float fA = sA + ett[j];
    float fV = sV + ett[j];
    float gA[NK], gV[NK];
#pragma unroll
    for (int i = 0; i < NK; i++) {
        gA[i] = __shfl_sync(0xffffffffu, fA, i);
        gV[i] = __shfl_sync(0xffffffffu, fV, i);
    }
    __syncwarp();
    if (lane == 0) {
        float mA = gA[0];
#pragma unroll
        for (int i = 1; i < NK; i++) mA = fmaxf(mA, gA[i]);
        float ssum = 0.f;
#pragma unroll
        for (int i = 0; i < NK; i++) ssum += __expf(gA[i] - mA);
        float denom = mA + __logf(ssum);
        int bl = 0; float mV = gV[0];
#pragma unroll
        for (int i = 1; i < NK; i++) { if (gV[i] > mV) { mV = gV[i]; bl = i; } }
        num += ett[lab[len - 1]];
        d_loss_partial[b] = num - denom;
        int cur = bl;
        d_preds[b * NT + NT - 1] = (NT - 1 < len) ? cur : 0;
        for (int t = NT - 2; t >= 0; t--) {
            if (t + 1 < len) cur = (int)hist[t + 1][cur];
            d_preds[b * NT + t] = (t < len) ? cur : 0;
        }
    }
}

__global__ void k_loss() {
    float s = 0.f;
    for (int i = 0; i < NB; i++) s += d_loss_partial[i];
    d_loss = -s / (float)NB;
}

// output layout: [loss(1), preds(B*T), feats(B*T*2H)] as float32, prefix-safe.
__global__ void k_writeout(float* __restrict__ out, int n) {
    int i = blockIdx.x * 256 + threadIdx.x;
    if (i >= n) return;
    float v = 0.f;
    if (i == 0) v = d_loss;
    else if (i < 1 + NB * NT) v = (float)d_preds[i - 1];
    else if (i < 1 + NB * NT + NB * NT * 2 * NH) v = d_feats[i - 1 - NB * NT];
    out[i] = v;
}

extern "C" void kernel_launch(void* const* d_in, const int* in_sizes, int n_in,
                              void* d_out, int out_size) {
    const int* widx = (const int*)d_in[0];
    const int* lens = (const int*)d_in[1];
    const int* labels = (const int*)d_in[2];
    const float* wvec = (const float*)d_in[3];
    const float* Wih_f = (const float*)d_in[4];
    const float* Whh_f = (const float*)d_in[5];
    const float* b_f = (const float*)d_in[6];
    const float* Wih_b = (const float*)d_in[7];
    const float* Whh_b = (const float*)d_in[8];
    const float* b_b = (const float*)d_in[9];
    const float* Wout = (const float*)d_in[10];
    const float* bout = (const float*)d_in[11];
    const float* stt = (const float*)d_in[12];
    const float* ett = (const float*)d_in[13];
    const float* trans = (const float*)d_in[14];

    k_init<<<16, 256>>>();                      // launch 0

    dim3 gg(NGATE / 128, NT, 2);
    k_gx<<<gg, 256>>>(widx, lens, wvec, Wih_f, b_f, Wih_b, b_b);  // launch 1

    k_nop<<<1, 32>>>();                         // launch 2 (pads ncu slot)

    int smem_bytes = LSTM_SMEM_FLOATS * 4;
    cudaFuncSetAttribute(k_lstm, cudaFuncAttributeMaxDynamicSharedMemorySize,
                         smem_bytes);
    k_lstm<<<NCTA, 128, smem_bytes>>>(Whh_f, Whh_b);  // launch 3 <- profiled

    dim3 gf(NT, NH / 64, 2);
    k_feats<<<gf, 256>>>(lens);

    k_emis<<<NB * NT / 8, 256>>>(Wout, bout);
    k_crf<<<NB, 32>>>(lens, labels, stt, ett, trans);
    k_loss<<<1, 1>>>();

    k_writeout<<<(out_size + 255) / 256, 256>>>((float*)d_out, out_size);
}